// round 12
// baseline (speedup 1.0000x reference)
#include <cuda_runtime.h>
#include <cuda_fp16.h>
#include <math.h>
#include <stdint.h>

#define T_SEQ 200
#define BATCH 128
#define MROWS (T_SEQ * BATCH)   // 25600
#define XS 4608                 // xg row stride (fp32)

// ---- device-global scratch ----
__device__ float  g_xga[(size_t)MROWS * XS];
__device__ float  g_xgb[(size_t)MROWS * XS];
__device__ __half g_ah[(size_t)(T_SEQ + 1) * BATCH * 1152];  // h plane (fp16)
__device__ __half g_wbh[(size_t)4608 * 1152];                // recurrent weight plane
__device__ __half g_wbg[(size_t)4608 * 1152];                // next-layer input weight plane
__device__ unsigned g_flags[512];

// ===========================================================================
// PTX helpers (sm_80-era, safe on plain sm_103 target)
// ===========================================================================
__device__ __forceinline__ uint32_t smem_u32(const void* p) {
    uint32_t a;
    asm("{ .reg .u64 t; cvta.to.shared.u64 t, %1; cvt.u32.u64 %0, t; }" : "=r"(a) : "l"(p));
    return a;
}
__device__ __forceinline__ void cp16(uint32_t s, const void* g) {
    asm volatile("cp.async.cg.shared.global [%0], [%1], 16;" :: "r"(s), "l"(g));
}
__device__ __forceinline__ void cp_commit() {
    asm volatile("cp.async.commit_group;");
}
template <int N> __device__ __forceinline__ void cp_wait() {
    asm volatile("cp.async.wait_group %0;" :: "n"(N));
}
__device__ __forceinline__ void ldsm4(uint32_t* r, uint32_t a) {
    asm volatile("ldmatrix.sync.aligned.m8n8.x4.shared.b16 {%0,%1,%2,%3}, [%4];"
        : "=r"(r[0]), "=r"(r[1]), "=r"(r[2]), "=r"(r[3]) : "r"(a));
}
__device__ __forceinline__ void mma_h(float* d, const uint32_t* a, uint32_t b0, uint32_t b1) {
    asm volatile("mma.sync.aligned.m16n8k16.row.col.f32.f16.f16.f32 "
        "{%0,%1,%2,%3}, {%4,%5,%6,%7}, {%8,%9}, {%0,%1,%2,%3};"
        : "+f"(d[0]), "+f"(d[1]), "+f"(d[2]), "+f"(d[3])
        : "r"(a[0]), "r"(a[1]), "r"(a[2]), "r"(a[3]), "r"(b0), "r"(b1));
}
__device__ __forceinline__ void st_rel(unsigned* p, unsigned v) {
    asm volatile("st.global.release.gpu.u32 [%0], %1;" :: "l"(p), "r"(v) : "memory");
}
__device__ __forceinline__ unsigned ld_acq(const unsigned* p) {
    unsigned v;
    asm volatile("ld.global.acquire.gpu.u32 %0, [%1];" : "=r"(v) : "l"(p) : "memory");
    return v;
}
__device__ __forceinline__ float sigm(float x) { return 1.0f / (1.0f + expf(-x)); }

// ===========================================================================
// Pre-convert kernels
// ===========================================================================
__global__ void embed_split(const int* __restrict__ tokens,
                            const float* __restrict__ emb,
                            __half* __restrict__ ah) {
    int row = blockIdx.x;
    int tok = tokens[row];
    const float* src = emb + (size_t)tok * 400;
    __half* dh = ah + (size_t)row * 416;
    for (int i = threadIdx.x; i < 416; i += blockDim.x) {
        float v = (i < 400) ? src[i] : 0.0f;
        dh[i] = __float2half_rn(v);
    }
}

// convert + gate-permute weights: out row n = (4j+g) <- src row (g*H+j); pad k>=K
__global__ void split_w(const float* __restrict__ W,
                        __half* __restrict__ bh,
                        int H, int K, int KP) {
    int id = blockIdx.x * 256 + threadIdx.x;
    int total = 4 * H * KP;
    if (id >= total) return;
    int n = id / KP, k = id - n * KP;
    float v = (k < K) ? W[(size_t)((n & 3) * H + (n >> 2)) * K + k] : 0.0f;
    bh[id] = __float2half_rn(v);
}

// ===========================================================================
// gemm_half (layer 0 only): xg = A @ Wperm^T + biasperm, stride XS.
// CTA 128x128, 4 warps (warp 64x64), K-chunk 32, 3-stage cp.async.
// ===========================================================================
#define GS 3
#define G_STG 10240
#define GEMM_SMEM (GS * G_STG * 2 + 512)

extern __shared__ __half hsm[];

__device__ __forceinline__ void g_load(uint32_t smb, int stage,
    const __half* __restrict__ Ah, const __half* __restrict__ Bh,
    int m0, int n0, int KP, int k0, int tid)
{
#pragma unroll
    for (int it = 0; it < 4; ++it) {
        int g = tid + it * 128;
        int r = g >> 2, cg = g & 3;
        cp16(smb + 2 * (stage * G_STG + r * 40 + cg * 8),
             Ah + (size_t)(m0 + r) * KP + k0 + cg * 8);
    }
#pragma unroll
    for (int it = 0; it < 4; ++it) {
        int g = tid + it * 128;
        int r = g >> 2, cg = g & 3;
        cp16(smb + 2 * (stage * G_STG + 5120 + r * 40 + cg * 8),
             Bh + (size_t)(n0 + r) * KP + k0 + cg * 8);
    }
}

__global__ __launch_bounds__(128) void gemm_half(
    const __half* __restrict__ Ah, const __half* __restrict__ Bh,
    const float* __restrict__ bias, float* __restrict__ C,
    int Ntot, int KP, int H)
{
    const int tid = threadIdx.x;
    const int lane = tid & 31, wid = tid >> 5;
    const int qt = lane & 3, qd = lane >> 2;
    const int n0 = blockIdx.x * 128;
    const int m0 = blockIdx.y * 128;
    const int wm = (wid >> 1) * 64, wn = (wid & 1) * 64;
    const uint32_t smb = smem_u32(hsm);

    float* bs = (float*)(hsm + GS * G_STG);
    {
        int n = n0 + tid;
        bs[tid] = (n < Ntot) ? bias[(size_t)(n & 3) * H + (n >> 2)] : 0.0f;
    }

    float acc[4][8][4] = {};
    const int nt = KP / 32;

#pragma unroll
    for (int s = 0; s < GS - 1; ++s) {
        g_load(smb, s, Ah, Bh, m0, n0, KP, s * 32, tid);
        cp_commit();
    }

    for (int i = 0; i < nt; ++i) {
        if (i + GS - 1 < nt)
            g_load(smb, (i + GS - 1) % GS, Ah, Bh, m0, n0, KP, (i + GS - 1) * 32, tid);
        cp_commit();
        cp_wait<GS - 1>();
        __syncthreads();

        const uint32_t sb = smb + 2 * ((i % GS) * G_STG);
#pragma unroll
        for (int s = 0; s < 2; ++s) {
            const int k0 = s * 16;
            uint32_t af[4][4];
#pragma unroll
            for (int mt = 0; mt < 4; ++mt) {
                uint32_t arow = wm + mt * 16 + (lane & 15);
                uint32_t acol = k0 + (lane >> 4) * 8;
                ldsm4(af[mt], sb + 2 * (arow * 40 + acol));
            }
#pragma unroll
            for (int gp = 0; gp < 4; ++gp) {
                uint32_t brow = wn + gp * 16 + ((lane >> 4) & 1) * 8 + (lane & 7);
                uint32_t bcol = k0 + ((lane >> 3) & 1) * 8;
                uint32_t tb[4];
                ldsm4(tb, sb + 2 * (5120u + brow * 40 + bcol));
#pragma unroll
                for (int mt = 0; mt < 4; ++mt)
#pragma unroll
                    for (int j = 0; j < 2; ++j)
                        mma_h(acc[mt][gp * 2 + j], af[mt], tb[j * 2], tb[j * 2 + 1]);
            }
        }
        __syncthreads();
    }

#pragma unroll
    for (int mt = 0; mt < 4; ++mt) {
        int row = m0 + wm + mt * 16 + qd;
#pragma unroll
        for (int ntl = 0; ntl < 8; ++ntl) {
            int cl = wn + ntl * 8 + 2 * qt;
            int col = n0 + cl;
            if (col < Ntot) {
                float b0 = bs[cl], b1 = bs[cl + 1];
                float2 v0 = make_float2(acc[mt][ntl][0] + b0, acc[mt][ntl][1] + b1);
                float2 v1 = make_float2(acc[mt][ntl][2] + b0, acc[mt][ntl][3] + b1);
                *(float2*)(C + (size_t)row * XS + col) = v0;
                *(float2*)(C + (size_t)(row + 8) * XS + col) = v1;
            }
        }
    }
}

// ===========================================================================
// lstm_persist (fused): per step, the SMEM A tile (h) feeds BOTH the
// recurrent gates (32 cols) AND the next layer's input GEMM (NG cols),
// whose result (xg row t-1 + bias) streams to xgn. One trailing gemm-only
// iteration covers the last output row. K-chunk 96, 2 stages.
// SMEM (halves): W[64][WSTR] | stages[2][A 128x104] | xg 128x36 f32 | biasg 32 f32
// ===========================================================================
#define LKC 96
#define LSTG 13312u   // halves per stage (128 x 104)

__global__ __launch_bounds__(256) void lstm_persist(
    const float* __restrict__ xg,     // [T][B][XS] this layer's input gates
    float* __restrict__ xgn,          // [T][B][XS] next layer's input gates (or null)
    __half* __restrict__ ah,          // [T+1][B][KP]
    const __half* __restrict__ wR,    // recurrent weight plane
    const __half* __restrict__ wG,    // next-layer input weight plane (or null)
    const float* __restrict__ biasn,  // next-layer bias (or null)
    float* __restrict__ out,          // [T][B][H]
    unsigned* __restrict__ flags,
    int H, int KP, int NG, int Nnext, int Hnext)
{
    const int Ntot = 4 * H;
    const int WSTR = KP + 8;
    const int tid = threadIdx.x;
    const int lane = tid & 31, wid = tid >> 5;
    const int qt = lane & 3, qd = lane >> 2;
    const int n0 = blockIdx.x * 32;
    const int n0g = blockIdx.x * NG;
    const int wm = (wid >> 1) * 32, wn = (wid & 1) * 16;
    const uint32_t smb = smem_u32(hsm);
    const uint32_t SOFF = 64u * (uint32_t)WSTR;        // stages base (halves)
    const uint32_t XOFF = SOFF + 2u * LSTG;            // xg tile base (halves)
    const uint32_t BOFF = XOFF + 9216u;                // next-bias base (halves)
    const int nt = KP / LKC;
    const unsigned nCTA = gridDim.x;
    const bool gwarp = (NG > 0) && (n0g < Nnext) && (wn < NG);

    // ---- preload weight tiles into SMEM ----
    {
        const int kops = KP / 8;
        for (int i = tid; i < 32 * kops; i += 256) {
            int r = i / kops, c = (i - r * kops) * 8;
            cp16(smb + 2 * (uint32_t)(r * WSTR + c), wR + (size_t)(n0 + r) * KP + c);
        }
        if (NG > 0) {
            for (int i = tid; i < 32 * kops; i += 256) {
                int r = i / kops, c = (i - r * kops) * 8;
                cp16(smb + 2 * (uint32_t)((32 + r) * WSTR + c),
                     wG + (size_t)(n0g + r) * KP + c);
            }
        }
        cp_commit();
        cp_wait<0>();
        __syncthreads();
    }
    // next-layer bias slice
    float* bgs = (float*)(hsm + BOFF);
    if (NG > 0 && tid < NG) {
        int col = n0g + tid;
        bgs[tid] = (col < Nnext) ? biasn[(size_t)(col & 3) * Hnext + (col >> 2)] : 0.0f;
    }

    float c4[4] = {0.f, 0.f, 0.f, 0.f};
    const int b = wm + lane;
    const int nbase = n0 + wn;
    const float* xsm = (const float*)(hsm + XOFF);
    const int tEnd = T_SEQ + (NG > 0 ? 1 : 0);

#define PL_LOAD(STAGE, K0)                                                    \
    {                                                                         \
        _Pragma("unroll")                                                     \
        for (int it = 0; it < 6; ++it) {                                      \
            int g = tid + it * 256;                                           \
            int r = g / 12, c = g - r * 12;                                   \
            cp16(smb + 2 * (SOFF + (STAGE) * LSTG + r * 104u + c * 8u),       \
                 hH + (size_t)r * KP + (K0) + c * 8);                         \
        }                                                                     \
    }

    for (int t = 0; t < tEnd; ++t) {
        const bool rec = (t < T_SEQ);
        const __half* hH = ah + (size_t)t * BATCH * KP;

        float acc[2][2][4] = {};
        float accg[2][2][4] = {};

        // first group: xg tile (this layer's gates) + A chunk 0
        if (rec) {
            const float* xgt = xg + (size_t)t * BATCH * XS;
#pragma unroll
            for (int it = 0; it < 4; ++it) {
                int g = tid + it * 256;
                int r = g >> 3, c = g & 7;
                int cb = n0 + c * 4;
                if (cb + 4 <= Ntot)
                    cp16(smb + 2 * XOFF + (uint32_t)(r * 144 + c * 16),
                         xgt + (size_t)r * XS + cb);
            }
        }
        PL_LOAD(0, 0);
        cp_commit();

        for (int i = 0; i < nt; ++i) {
            if (i + 1 < nt) PL_LOAD((i + 1) & 1, (i + 1) * LKC);
            cp_commit();
            cp_wait<1>();
            __syncthreads();

            const uint32_t sa = smb + 2 * (SOFF + (uint32_t)(i & 1) * LSTG);
            const int kb = i * LKC;
#pragma unroll
            for (int s = 0; s < 6; ++s) {
                const int k0 = s * 16;
                uint32_t af[2][4];
#pragma unroll
                for (int mt = 0; mt < 2; ++mt) {
                    uint32_t arow = wm + mt * 16 + (lane & 15);
                    uint32_t acol = k0 + (lane >> 4) * 8;
                    ldsm4(af[mt], sa + 2 * (arow * 104 + acol));
                }
                const uint32_t bcol = (uint32_t)(kb + k0) + ((lane >> 3) & 1) * 8;
                const uint32_t brbase = ((lane >> 4) & 1) * 8 + (lane & 7);
                {
                    uint32_t t4[4];
                    ldsm4(t4, smb + 2 * ((wn + brbase) * (uint32_t)WSTR + bcol));
#pragma unroll
                    for (int mt = 0; mt < 2; ++mt) {
                        mma_h(acc[mt][0], af[mt], t4[0], t4[1]);
                        mma_h(acc[mt][1], af[mt], t4[2], t4[3]);
                    }
                }
                if (gwarp) {
                    uint32_t t4[4];
                    ldsm4(t4, smb + 2 * ((32u + wn + brbase) * (uint32_t)WSTR + bcol));
#pragma unroll
                    for (int mt = 0; mt < 2; ++mt) {
                        mma_h(accg[mt][0], af[mt], t4[0], t4[1]);
                        mma_h(accg[mt][1], af[mt], t4[2], t4[3]);
                    }
                }
            }
            __syncthreads();
        }

        // ---- recurrent gate epilogue ----
        if (rec) {
            float* gsm = (float*)(hsm + SOFF) + wid * (32 * 20);
#pragma unroll
            for (int mt = 0; mt < 2; ++mt)
#pragma unroll
                for (int ntl = 0; ntl < 2; ++ntl) {
                    int r0 = mt * 16 + qd;
                    int c0 = ntl * 8 + 2 * qt;
                    gsm[r0 * 20 + c0]           = acc[mt][ntl][0];
                    gsm[r0 * 20 + c0 + 1]       = acc[mt][ntl][1];
                    gsm[(r0 + 8) * 20 + c0]     = acc[mt][ntl][2];
                    gsm[(r0 + 8) * 20 + c0 + 1] = acc[mt][ntl][3];
                }
            __syncwarp();

            __half* nH = ah + (size_t)(t + 1) * BATCH * KP;
            float* ob = out + ((size_t)t * BATCH + b) * H;
#pragma unroll
            for (int u = 0; u < 4; ++u) {
                int colg = nbase + 4 * u;
                if (colg < Ntot) {
                    int j = colg >> 2;
                    float4 g4 = *(float4*)&gsm[lane * 20 + 4 * u];
                    float4 x4 = *(const float4*)&xsm[b * 36 + wn + 4 * u];
                    float pi = g4.x + x4.x;
                    float pf = g4.y + x4.y;
                    float pg = g4.z + x4.z;
                    float po = g4.w + x4.w;
                    float cc = sigm(pf) * c4[u] + sigm(pi) * tanhf(pg);
                    c4[u] = cc;
                    float h = sigm(po) * tanhf(cc);
                    ob[j] = h;
                    nH[(size_t)b * KP + j] = __float2half_rn(h);
                }
            }
        }

        // ---- fused next-layer xg epilogue (row t-1) ----
        if (gwarp && t >= 1) {
            float* xrow = xgn + (size_t)(t - 1) * BATCH * XS;
#pragma unroll
            for (int mt = 0; mt < 2; ++mt) {
                int row = wm + mt * 16 + qd;
#pragma unroll
                for (int ntl = 0; ntl < 2; ++ntl) {
                    int cl = wn + ntl * 8 + 2 * qt;
                    int col = n0g + cl;
                    if (col < Nnext) {
                        float b0 = bgs[cl], b1 = bgs[cl + 1];
                        float2 v0 = make_float2(accg[mt][ntl][0] + b0, accg[mt][ntl][1] + b1);
                        float2 v1 = make_float2(accg[mt][ntl][2] + b0, accg[mt][ntl][3] + b1);
                        *(float2*)(xrow + (size_t)row * XS + col) = v0;
                        *(float2*)(xrow + (size_t)(row + 8) * XS + col) = v1;
                    }
                }
            }
        }

        // ---- all-poll grid barrier ----
        if (rec) {
            __threadfence();
            __syncthreads();
            const unsigned epoch = (unsigned)(t + 1);
            if (tid == 0) st_rel(flags + blockIdx.x, epoch);
            if (tid < nCTA) {
                while (ld_acq(flags + tid) < epoch) __nanosleep(32);
            }
            __syncthreads();
        }
    }
#undef PL_LOAD
}

// ---------------------------------------------------------------------------
extern "C" void kernel_launch(void* const* d_in, const int* in_sizes, int n_in,
                              void* d_out, int out_size) {
    const int*   tokens = (const int*)d_in[0];
    const float* emb    = (const float*)d_in[1];
    const float* Wih[3] = {(const float*)d_in[2], (const float*)d_in[5], (const float*)d_in[8]};
    const float* Whh[3] = {(const float*)d_in[3], (const float*)d_in[6], (const float*)d_in[9]};
    const float* bb[3]  = {(const float*)d_in[4], (const float*)d_in[7], (const float*)d_in[10]};
    float* out = (float*)d_out;

    float *xga, *xgb;
    __half *ah, *wbh, *wbg;
    unsigned* flags;
    cudaGetSymbolAddress((void**)&xga, g_xga);
    cudaGetSymbolAddress((void**)&xgb, g_xgb);
    cudaGetSymbolAddress((void**)&ah,  g_ah);
    cudaGetSymbolAddress((void**)&wbh, g_wbh);
    cudaGetSymbolAddress((void**)&wbg, g_wbg);
    cudaGetSymbolAddress((void**)&flags, g_flags);

    const int PSMEM_MAX = (64 * (1152 + 8) + 2 * (int)LSTG + 9216 + 64) * 2;  // 220288
    cudaFuncSetAttribute(gemm_half,    cudaFuncAttributeMaxDynamicSharedMemorySize, GEMM_SMEM);
    cudaFuncSetAttribute(lstm_persist, cudaFuncAttributeMaxDynamicSharedMemorySize, PSMEM_MAX);

    embed_split<<<MROWS, 128>>>(tokens, emb, ah);

    // ---- layer 0 input GEMM (only standalone GEMM remaining) ----
    split_w<<<(4 * 1150 * 416 + 255) / 256, 256>>>(Wih[0], wbh, 1150, 400, 416);
    {
        dim3 gg((4600 + 127) / 128, MROWS / 128);
        gemm_half<<<gg, 128, GEMM_SMEM>>>(ah, wbh, bb[0], xga, 4600, 416, 1150);
    }

    const int Hs[3]    = {1150, 1150, 400};
    const int HPs[3]   = {1152, 1152, 480};
    const int NGs[3]   = {32, 16, 0};
    const int Nnx[3]   = {4600, 1600, 0};
    const int Hnx[3]   = {1150, 400, 1};
    const size_t outoff[3] = {0, (size_t)MROWS * 1150, (size_t)MROWS * 1150 * 2};
    float* xgin[3]  = {xga, xgb, xga};
    float* xgout[3] = {xgb, xga, nullptr};

    for (int l = 0; l < 3; ++l) {
        const int H = Hs[l], HP = HPs[l], N = 4 * H;

        cudaMemsetAsync(ah, 0, (size_t)(T_SEQ + 1) * BATCH * HP * 2);
        cudaMemsetAsync(flags, 0, 512 * sizeof(unsigned));

        // recurrent weights (this layer) + input weights (next layer)
        split_w<<<(4 * H * HP + 255) / 256, 256>>>(Whh[l], wbh, H, H, HP);
        if (l < 2)
            split_w<<<(4 * Hnx[l] * HP + 255) / 256, 256>>>(Wih[l + 1], wbg,
                                                            Hnx[l], H, HP);

        const int nblk = (N + 31) / 32;   // 144, 144, 50
        const int psm = (64 * (HP + 8) + 2 * (int)LSTG + 9216 + 64) * 2;
        lstm_persist<<<nblk, 256, psm>>>(
            xgin[l], xgout[l], ah, wbh, (l < 2) ? wbg : nullptr,
            (l < 2) ? bb[l + 1] : nullptr,
            out + outoff[l], flags, H, HP, NGs[l], Nnx[l], Hnx[l]);
    }
}

// round 13
// speedup vs baseline: 1.0365x; 1.0365x over previous
#include <cuda_runtime.h>
#include <cuda_fp16.h>
#include <math.h>
#include <stdint.h>

#define T_SEQ 200
#define BATCH 128
#define MROWS (T_SEQ * BATCH)   // 25600
#define XS 4608                 // xg row stride (fp32)

// ---- device-global scratch ----
__device__ float  g_xga[(size_t)MROWS * XS];
__device__ float  g_xgb[(size_t)MROWS * XS];
__device__ __half g_ah[(size_t)(T_SEQ + 1) * BATCH * 1152];  // h plane (fp16)
__device__ __half g_wbh[(size_t)4608 * 1152];                // recurrent weight plane
__device__ __half g_wbg[(size_t)4608 * 1152];                // next-layer input weight plane
__device__ unsigned g_flags[512];

// ===========================================================================
// PTX helpers (sm_80-era, safe on plain sm_103 target)
// ===========================================================================
__device__ __forceinline__ uint32_t smem_u32(const void* p) {
    uint32_t a;
    asm("{ .reg .u64 t; cvta.to.shared.u64 t, %1; cvt.u32.u64 %0, t; }" : "=r"(a) : "l"(p));
    return a;
}
__device__ __forceinline__ void cp16(uint32_t s, const void* g) {
    asm volatile("cp.async.cg.shared.global [%0], [%1], 16;" :: "r"(s), "l"(g));
}
__device__ __forceinline__ void cp_commit() {
    asm volatile("cp.async.commit_group;");
}
template <int N> __device__ __forceinline__ void cp_wait() {
    asm volatile("cp.async.wait_group %0;" :: "n"(N));
}
__device__ __forceinline__ void ldsm4(uint32_t* r, uint32_t a) {
    asm volatile("ldmatrix.sync.aligned.m8n8.x4.shared.b16 {%0,%1,%2,%3}, [%4];"
        : "=r"(r[0]), "=r"(r[1]), "=r"(r[2]), "=r"(r[3]) : "r"(a));
}
__device__ __forceinline__ void mma_h(float* d, const uint32_t* a, uint32_t b0, uint32_t b1) {
    asm volatile("mma.sync.aligned.m16n8k16.row.col.f32.f16.f16.f32 "
        "{%0,%1,%2,%3}, {%4,%5,%6,%7}, {%8,%9}, {%0,%1,%2,%3};"
        : "+f"(d[0]), "+f"(d[1]), "+f"(d[2]), "+f"(d[3])
        : "r"(a[0]), "r"(a[1]), "r"(a[2]), "r"(a[3]), "r"(b0), "r"(b1));
}
__device__ __forceinline__ void st_rel(unsigned* p, unsigned v) {
    asm volatile("st.global.release.gpu.u32 [%0], %1;" :: "l"(p), "r"(v) : "memory");
}
__device__ __forceinline__ unsigned ld_acq(const unsigned* p) {
    unsigned v;
    asm volatile("ld.global.acquire.gpu.u32 %0, [%1];" : "=r"(v) : "l"(p) : "memory");
    return v;
}
__device__ __forceinline__ float sigm(float x) { return 1.0f / (1.0f + expf(-x)); }

// ===========================================================================
// Pre-convert kernels
// ===========================================================================
__global__ void embed_split(const int* __restrict__ tokens,
                            const float* __restrict__ emb,
                            __half* __restrict__ ah) {
    int row = blockIdx.x;
    int tok = tokens[row];
    const float* src = emb + (size_t)tok * 400;
    __half* dh = ah + (size_t)row * 416;
    for (int i = threadIdx.x; i < 416; i += blockDim.x) {
        float v = (i < 400) ? src[i] : 0.0f;
        dh[i] = __float2half_rn(v);
    }
}

// convert + gate-permute weights: out row n = (4j+g) <- src row (g*H+j); pad k>=K
__global__ void split_w(const float* __restrict__ W,
                        __half* __restrict__ bh,
                        int H, int K, int KP) {
    int id = blockIdx.x * 256 + threadIdx.x;
    int total = 4 * H * KP;
    if (id >= total) return;
    int n = id / KP, k = id - n * KP;
    float v = (k < K) ? W[(size_t)((n & 3) * H + (n >> 2)) * K + k] : 0.0f;
    bh[id] = __float2half_rn(v);
}

// ===========================================================================
// gemm_half (layer 0 only): xg = A @ Wperm^T + biasperm, stride XS.
// CTA 128x128, 4 warps (warp 64x64), K-chunk 32, 3-stage cp.async.
// ===========================================================================
#define GS 3
#define G_STG 10240
#define GEMM_SMEM (GS * G_STG * 2 + 512)

extern __shared__ __half hsm[];

__device__ __forceinline__ void g_load(uint32_t smb, int stage,
    const __half* __restrict__ Ah, const __half* __restrict__ Bh,
    int m0, int n0, int KP, int k0, int tid)
{
#pragma unroll
    for (int it = 0; it < 4; ++it) {
        int g = tid + it * 128;
        int r = g >> 2, cg = g & 3;
        cp16(smb + 2 * (stage * G_STG + r * 40 + cg * 8),
             Ah + (size_t)(m0 + r) * KP + k0 + cg * 8);
    }
#pragma unroll
    for (int it = 0; it < 4; ++it) {
        int g = tid + it * 128;
        int r = g >> 2, cg = g & 3;
        cp16(smb + 2 * (stage * G_STG + 5120 + r * 40 + cg * 8),
             Bh + (size_t)(n0 + r) * KP + k0 + cg * 8);
    }
}

__global__ __launch_bounds__(128) void gemm_half(
    const __half* __restrict__ Ah, const __half* __restrict__ Bh,
    const float* __restrict__ bias, float* __restrict__ C,
    int Ntot, int KP, int H)
{
    const int tid = threadIdx.x;
    const int lane = tid & 31, wid = tid >> 5;
    const int qt = lane & 3, qd = lane >> 2;
    const int n0 = blockIdx.x * 128;
    const int m0 = blockIdx.y * 128;
    const int wm = (wid >> 1) * 64, wn = (wid & 1) * 64;
    const uint32_t smb = smem_u32(hsm);

    float* bs = (float*)(hsm + GS * G_STG);
    {
        int n = n0 + tid;
        bs[tid] = (n < Ntot) ? bias[(size_t)(n & 3) * H + (n >> 2)] : 0.0f;
    }

    float acc[4][8][4] = {};
    const int nt = KP / 32;

#pragma unroll
    for (int s = 0; s < GS - 1; ++s) {
        g_load(smb, s, Ah, Bh, m0, n0, KP, s * 32, tid);
        cp_commit();
    }

    for (int i = 0; i < nt; ++i) {
        if (i + GS - 1 < nt)
            g_load(smb, (i + GS - 1) % GS, Ah, Bh, m0, n0, KP, (i + GS - 1) * 32, tid);
        cp_commit();
        cp_wait<GS - 1>();
        __syncthreads();

        const uint32_t sb = smb + 2 * ((i % GS) * G_STG);
#pragma unroll
        for (int s = 0; s < 2; ++s) {
            const int k0 = s * 16;
            uint32_t af[4][4];
#pragma unroll
            for (int mt = 0; mt < 4; ++mt) {
                uint32_t arow = wm + mt * 16 + (lane & 15);
                uint32_t acol = k0 + (lane >> 4) * 8;
                ldsm4(af[mt], sb + 2 * (arow * 40 + acol));
            }
#pragma unroll
            for (int gp = 0; gp < 4; ++gp) {
                uint32_t brow = wn + gp * 16 + ((lane >> 4) & 1) * 8 + (lane & 7);
                uint32_t bcol = k0 + ((lane >> 3) & 1) * 8;
                uint32_t tb[4];
                ldsm4(tb, sb + 2 * (5120u + brow * 40 + bcol));
#pragma unroll
                for (int mt = 0; mt < 4; ++mt)
#pragma unroll
                    for (int j = 0; j < 2; ++j)
                        mma_h(acc[mt][gp * 2 + j], af[mt], tb[j * 2], tb[j * 2 + 1]);
            }
        }
        __syncthreads();
    }

#pragma unroll
    for (int mt = 0; mt < 4; ++mt) {
        int row = m0 + wm + mt * 16 + qd;
#pragma unroll
        for (int ntl = 0; ntl < 8; ++ntl) {
            int cl = wn + ntl * 8 + 2 * qt;
            int col = n0 + cl;
            if (col < Ntot) {
                float b0 = bs[cl], b1 = bs[cl + 1];
                float2 v0 = make_float2(acc[mt][ntl][0] + b0, acc[mt][ntl][1] + b1);
                float2 v1 = make_float2(acc[mt][ntl][2] + b0, acc[mt][ntl][3] + b1);
                *(float2*)(C + (size_t)row * XS + col) = v0;
                *(float2*)(C + (size_t)(row + 8) * XS + col) = v1;
            }
        }
    }
}

// ===========================================================================
// lstm_persist (fused): per step, the SMEM A tile (h) feeds BOTH the
// recurrent gates (32 cols) AND the next layer's input GEMM (NG cols),
// whose result (xg row t-1 + bias) streams to xgn. One trailing gemm-only
// iteration covers the last output row. K-chunk 96, 2 stages.
// SMEM (halves): W[64][WSTR] | stages[2][A 128x104] | xg 128x36 f32 | biasg 32 f32
// ===========================================================================
#define LKC 96
#define LSTG 13312u   // halves per stage (128 x 104)

__global__ __launch_bounds__(256) void lstm_persist(
    const float* __restrict__ xg,     // [T][B][XS] this layer's input gates
    float* __restrict__ xgn,          // [T][B][XS] next layer's input gates (or null)
    __half* __restrict__ ah,          // [T+1][B][KP]
    const __half* __restrict__ wR,    // recurrent weight plane
    const __half* __restrict__ wG,    // next-layer input weight plane (or null)
    const float* __restrict__ biasn,  // next-layer bias (or null)
    float* __restrict__ out,          // [T][B][H]
    unsigned* __restrict__ flags,
    int H, int KP, int NG, int Nnext, int Hnext)
{
    const int Ntot = 4 * H;
    const int WSTR = KP + 8;
    const int tid = threadIdx.x;
    const int lane = tid & 31, wid = tid >> 5;
    const int qt = lane & 3, qd = lane >> 2;
    const int n0 = blockIdx.x * 32;
    const int n0g = blockIdx.x * NG;
    const int wm = (wid >> 1) * 32, wn = (wid & 1) * 16;
    const uint32_t smb = smem_u32(hsm);
    const uint32_t SOFF = 64u * (uint32_t)WSTR;        // stages base (halves)
    const uint32_t XOFF = SOFF + 2u * LSTG;            // xg tile base (halves)
    const uint32_t BOFF = XOFF + 9216u;                // next-bias base (halves)
    const int nt = KP / LKC;
    const unsigned nCTA = gridDim.x;
    const bool gwarp = (NG > 0) && (n0g < Nnext) && (wn < NG);

    // ---- preload weight tiles into SMEM ----
    {
        const int kops = KP / 8;
        for (int i = tid; i < 32 * kops; i += 256) {
            int r = i / kops, c = (i - r * kops) * 8;
            cp16(smb + 2 * (uint32_t)(r * WSTR + c), wR + (size_t)(n0 + r) * KP + c);
        }
        if (NG > 0) {
            for (int i = tid; i < 32 * kops; i += 256) {
                int r = i / kops, c = (i - r * kops) * 8;
                cp16(smb + 2 * (uint32_t)((32 + r) * WSTR + c),
                     wG + (size_t)(n0g + r) * KP + c);
            }
        }
        cp_commit();
        cp_wait<0>();
        __syncthreads();
    }
    // next-layer bias slice
    float* bgs = (float*)(hsm + BOFF);
    if (NG > 0 && tid < NG) {
        int col = n0g + tid;
        bgs[tid] = (col < Nnext) ? biasn[(size_t)(col & 3) * Hnext + (col >> 2)] : 0.0f;
    }

    float c4[4] = {0.f, 0.f, 0.f, 0.f};
    const int b = wm + lane;
    const int nbase = n0 + wn;
    const float* xsm = (const float*)(hsm + XOFF);
    const int tEnd = T_SEQ + (NG > 0 ? 1 : 0);

#define PL_LOAD(STAGE, K0)                                                    \
    {                                                                         \
        _Pragma("unroll")                                                     \
        for (int it = 0; it < 6; ++it) {                                      \
            int g = tid + it * 256;                                           \
            int r = g / 12, c = g - r * 12;                                   \
            cp16(smb + 2 * (SOFF + (STAGE) * LSTG + r * 104u + c * 8u),       \
                 hH + (size_t)r * KP + (K0) + c * 8);                         \
        }                                                                     \
    }

    for (int t = 0; t < tEnd; ++t) {
        const bool rec = (t < T_SEQ);
        const __half* hH = ah + (size_t)t * BATCH * KP;

        float acc[2][2][4] = {};
        float accg[2][2][4] = {};

        // first group: xg tile (this layer's gates) + A chunk 0
        if (rec) {
            const float* xgt = xg + (size_t)t * BATCH * XS;
#pragma unroll
            for (int it = 0; it < 4; ++it) {
                int g = tid + it * 256;
                int r = g >> 3, c = g & 7;
                int cb = n0 + c * 4;
                if (cb + 4 <= Ntot)
                    cp16(smb + 2 * XOFF + (uint32_t)(r * 144 + c * 16),
                         xgt + (size_t)r * XS + cb);
            }
        }
        PL_LOAD(0, 0);
        cp_commit();

        for (int i = 0; i < nt; ++i) {
            if (i + 1 < nt) PL_LOAD((i + 1) & 1, (i + 1) * LKC);
            cp_commit();
            cp_wait<1>();
            __syncthreads();

            const uint32_t sa = smb + 2 * (SOFF + (uint32_t)(i & 1) * LSTG);
            const int kb = i * LKC;
#pragma unroll
            for (int s = 0; s < 6; ++s) {
                const int k0 = s * 16;
                uint32_t af[2][4];
#pragma unroll
                for (int mt = 0; mt < 2; ++mt) {
                    uint32_t arow = wm + mt * 16 + (lane & 15);
                    uint32_t acol = k0 + (lane >> 4) * 8;
                    ldsm4(af[mt], sa + 2 * (arow * 104 + acol));
                }
                const uint32_t bcol = (uint32_t)(kb + k0) + ((lane >> 3) & 1) * 8;
                const uint32_t brbase = ((lane >> 4) & 1) * 8 + (lane & 7);
                {
                    uint32_t t4[4];
                    ldsm4(t4, smb + 2 * ((wn + brbase) * (uint32_t)WSTR + bcol));
#pragma unroll
                    for (int mt = 0; mt < 2; ++mt) {
                        mma_h(acc[mt][0], af[mt], t4[0], t4[1]);
                        mma_h(acc[mt][1], af[mt], t4[2], t4[3]);
                    }
                }
                if (gwarp) {
                    uint32_t t4[4];
                    ldsm4(t4, smb + 2 * ((32u + wn + brbase) * (uint32_t)WSTR + bcol));
#pragma unroll
                    for (int mt = 0; mt < 2; ++mt) {
                        mma_h(accg[mt][0], af[mt], t4[0], t4[1]);
                        mma_h(accg[mt][1], af[mt], t4[2], t4[3]);
                    }
                }
            }
            __syncthreads();
        }

        // ---- recurrent gate epilogue ----
        if (rec) {
            float* gsm = (float*)(hsm + SOFF) + wid * (32 * 20);
#pragma unroll
            for (int mt = 0; mt < 2; ++mt)
#pragma unroll
                for (int ntl = 0; ntl < 2; ++ntl) {
                    int r0 = mt * 16 + qd;
                    int c0 = ntl * 8 + 2 * qt;
                    gsm[r0 * 20 + c0]           = acc[mt][ntl][0];
                    gsm[r0 * 20 + c0 + 1]       = acc[mt][ntl][1];
                    gsm[(r0 + 8) * 20 + c0]     = acc[mt][ntl][2];
                    gsm[(r0 + 8) * 20 + c0 + 1] = acc[mt][ntl][3];
                }
            __syncwarp();

            __half* nH = ah + (size_t)(t + 1) * BATCH * KP;
            float* ob = out + ((size_t)t * BATCH + b) * H;
#pragma unroll
            for (int u = 0; u < 4; ++u) {
                int colg = nbase + 4 * u;
                if (colg < Ntot) {
                    int j = colg >> 2;
                    float4 g4 = *(float4*)&gsm[lane * 20 + 4 * u];
                    float4 x4 = *(const float4*)&xsm[b * 36 + wn + 4 * u];
                    float pi = g4.x + x4.x;
                    float pf = g4.y + x4.y;
                    float pg = g4.z + x4.z;
                    float po = g4.w + x4.w;
                    float cc = sigm(pf) * c4[u] + sigm(pi) * tanhf(pg);
                    c4[u] = cc;
                    float h = sigm(po) * tanhf(cc);
                    ob[j] = h;
                    nH[(size_t)b * KP + j] = __float2half_rn(h);
                }
            }
        }

        // ---- fused next-layer xg epilogue (row t-1) ----
        if (gwarp && t >= 1) {
            float* xrow = xgn + (size_t)(t - 1) * BATCH * XS;
#pragma unroll
            for (int mt = 0; mt < 2; ++mt) {
                int row = wm + mt * 16 + qd;
#pragma unroll
                for (int ntl = 0; ntl < 2; ++ntl) {
                    int cl = wn + ntl * 8 + 2 * qt;
                    int col = n0g + cl;
                    if (col < Nnext) {
                        float b0 = bgs[cl], b1 = bgs[cl + 1];
                        float2 v0 = make_float2(accg[mt][ntl][0] + b0, accg[mt][ntl][1] + b1);
                        float2 v1 = make_float2(accg[mt][ntl][2] + b0, accg[mt][ntl][3] + b1);
                        *(float2*)(xrow + (size_t)row * XS + col) = v0;
                        *(float2*)(xrow + (size_t)(row + 8) * XS + col) = v1;
                    }
                }
            }
        }

        // ---- all-poll grid barrier ----
        if (rec) {
            __threadfence();
            __syncthreads();
            const unsigned epoch = (unsigned)(t + 1);
            if (tid == 0) st_rel(flags + blockIdx.x, epoch);
            if (tid < nCTA) {
                while (ld_acq(flags + tid) < epoch) __nanosleep(32);
            }
            __syncthreads();
        }
    }
#undef PL_LOAD
}

// ---------------------------------------------------------------------------
extern "C" void kernel_launch(void* const* d_in, const int* in_sizes, int n_in,
                              void* d_out, int out_size) {
    const int*   tokens = (const int*)d_in[0];
    const float* emb    = (const float*)d_in[1];
    const float* Wih[3] = {(const float*)d_in[2], (const float*)d_in[5], (const float*)d_in[8]};
    const float* Whh[3] = {(const float*)d_in[3], (const float*)d_in[6], (const float*)d_in[9]};
    const float* bb[3]  = {(const float*)d_in[4], (const float*)d_in[7], (const float*)d_in[10]};
    float* out = (float*)d_out;

    float *xga, *xgb;
    __half *ah, *wbh, *wbg;
    unsigned* flags;
    cudaGetSymbolAddress((void**)&xga, g_xga);
    cudaGetSymbolAddress((void**)&xgb, g_xgb);
    cudaGetSymbolAddress((void**)&ah,  g_ah);
    cudaGetSymbolAddress((void**)&wbh, g_wbh);
    cudaGetSymbolAddress((void**)&wbg, g_wbg);
    cudaGetSymbolAddress((void**)&flags, g_flags);

    const int PSMEM_MAX = (64 * (1152 + 8) + 2 * (int)LSTG + 9216 + 64) * 2;  // 220288
    cudaFuncSetAttribute(gemm_half,    cudaFuncAttributeMaxDynamicSharedMemorySize, GEMM_SMEM);
    cudaFuncSetAttribute(lstm_persist, cudaFuncAttributeMaxDynamicSharedMemorySize, PSMEM_MAX);

    embed_split<<<MROWS, 128>>>(tokens, emb, ah);

    // ---- layer 0 input GEMM (only standalone GEMM remaining) ----
    split_w<<<(4 * 1150 * 416 + 255) / 256, 256>>>(Wih[0], wbh, 1150, 400, 416);
    {
        dim3 gg((4600 + 127) / 128, MROWS / 128);
        gemm_half<<<gg, 128, GEMM_SMEM>>>(ah, wbh, bb[0], xga, 4600, 416, 1150);
    }

    const int Hs[3]    = {1150, 1150, 400};
    const int HPs[3]   = {1152, 1152, 480};
    const int NGs[3]   = {32, 16, 0};
    const int Nnx[3]   = {4600, 1600, 0};
    const int Hnx[3]   = {1150, 400, 1};
    const size_t outoff[3] = {0, (size_t)MROWS * 1150, (size_t)MROWS * 1150 * 2};
    float* xgin[3]  = {xga, xgb, xga};
    float* xgout[3] = {xgb, xga, nullptr};

    for (int l = 0; l < 3; ++l) {
        const int H = Hs[l], HP = HPs[l], N = 4 * H;

        cudaMemsetAsync(ah, 0, (size_t)(T_SEQ + 1) * BATCH * HP * 2);
        cudaMemsetAsync(flags, 0, 512 * sizeof(unsigned));

        // recurrent weights (this layer) + input weights (next layer)
        split_w<<<(4 * H * HP + 255) / 256, 256>>>(Whh[l], wbh, H, H, HP);
        if (l < 2)
            split_w<<<(4 * Hnx[l] * HP + 255) / 256, 256>>>(Wih[l + 1], wbg,
                                                            Hnx[l], H, HP);

        const int nblk = (N + 31) / 32;   // 144, 144, 50
        const int psm = (64 * (HP + 8) + 2 * (int)LSTG + 9216 + 64) * 2;
        lstm_persist<<<nblk, 256, psm>>>(
            xgin[l], xgout[l], ah, wbh, (l < 2) ? wbg : nullptr,
            (l < 2) ? bb[l + 1] : nullptr,
            out + outoff[l], flags, H, HP, NGs[l], Nnx[l], Hnx[l]);
    }
}